// round 2
// baseline (speedup 1.0000x reference)
#include <cuda_runtime.h>

#define GH 32
#define GW 32
#define DD 768
#define NB 64
#define NPOS (GH * GW)
#define D4 (DD / 4)          // 192 float4 per position
#define NEH (GH * (GW - 1))  // 992 horizontal edges
#define NEV ((GH - 1) * GW)  // 992 vertical edges
#define NE (NEH + NEV)       // 1984 edges total

// Edge flags. Each flag is written (0 or 1) by exactly one block of
// edge_kernel every launch, so no zeroing pass and no cross-block races.
__device__ unsigned char g_eh[NEH];
__device__ unsigned char g_ev[NEV];

// ---------------------------------------------------------------------------
// Kernel 1: one block per edge. Loop over batches; break on first batch whose
// ||x[b,p0]-x[b,p1]||^2 > THRESHOLD^2 (=1.0). With typical inputs batch 0
// triggers, so each block does a single 6 KB pass. Flag written once, 0/1.
// 192 threads: one float4 per thread from each of the two positions.
// ---------------------------------------------------------------------------
__global__ __launch_bounds__(192) void edge_kernel(const float* __restrict__ x) {
    const int e = blockIdx.x;   // 0..1983 (first NEH horizontal, then vertical)
    const int t = threadIdx.x;  // 0..191

    int p0, p1;
    unsigned char* flag;
    if (e < NEH) {
        const int hh = e / (GW - 1);
        const int ww = e - hh * (GW - 1);
        p0 = hh * GW + ww;
        p1 = p0 + 1;
        flag = &g_eh[e];
    } else {
        const int e2 = e - NEH;
        p0 = e2;            // hh*GW + ww with ww in [0,GW)
        p1 = e2 + GW;
        flag = &g_ev[e2];
    }

    __shared__ float ws[6];
    __shared__ int done;
    if (t == 0) done = 0;
    __syncthreads();

    for (int b = 0; b < NB; b++) {
        const float4* a = (const float4*)(x + ((size_t)b * NPOS + p0) * DD);
        const float4* c = (const float4*)(x + ((size_t)b * NPOS + p1) * DD);
        const float4 va = a[t];
        const float4 vc = c[t];
        const float dx = va.x - vc.x;
        const float dy = va.y - vc.y;
        const float dz = va.z - vc.z;
        const float dw = va.w - vc.w;
        float s = dx * dx + dy * dy + dz * dz + dw * dw;

        #pragma unroll
        for (int off = 16; off > 0; off >>= 1)
            s += __shfl_down_sync(0xFFFFFFFFu, s, off);
        if ((t & 31) == 0) ws[t >> 5] = s;
        __syncthreads();
        if (t == 0) {
            const float tot = ws[0] + ws[1] + ws[2] + ws[3] + ws[4] + ws[5];
            if (tot > 1.0f) done = 1;  // THRESHOLD^2
        }
        __syncthreads();
        if (done) break;
    }

    if (t == 0) *flag = (unsigned char)done;
}

// ---------------------------------------------------------------------------
// Kernel 2: one block of 192 threads per (batch, position); thread t owns
// float4 #t of that position's 768-dim vector (3 KB, perfectly coalesced).
// The mask test is block-uniform: unmasked/boundary positions do a pure
// 3 KB copy with zero divergence; masked interior positions additionally
// load the 4 neighbors and blend with the reference's exact association:
//   0.5*c + 0.5*((((u+d)+l)+r)*0.25)
// ---------------------------------------------------------------------------
__global__ __launch_bounds__(192) void apply_kernel(const float* __restrict__ x,
                                                    float* __restrict__ out) {
    const unsigned int pos = blockIdx.x;        // b*NPOS + n, n = hh*32+ww
    const unsigned int t = threadIdx.x;         // 0..191
    const unsigned int n = pos & (NPOS - 1);
    const unsigned int hh = n >> 5;
    const unsigned int ww = n & 31;

    const float4* __restrict__ xin = (const float4*)x;
    float4* __restrict__ o = (float4*)out;
    const unsigned int i = pos * (unsigned)D4 + t;

    float4 c = xin[i];

    if (hh - 1u < (unsigned)(GH - 2) && ww - 1u < (unsigned)(GW - 2)) {
        const int m = (int)g_eh[hh * (GW - 1) + ww - 1] | (int)g_eh[hh * (GW - 1) + ww] |
                      (int)g_ev[(hh - 1) * GW + ww]     | (int)g_ev[hh * GW + ww];
        if (m) {  // block-uniform branch
            const float4 u = xin[i - (unsigned)(GW * D4)];
            const float4 d = xin[i + (unsigned)(GW * D4)];
            const float4 l = xin[i - (unsigned)D4];
            const float4 r = xin[i + (unsigned)D4];
            c.x = 0.5f * c.x + 0.5f * ((((u.x + d.x) + l.x) + r.x) * 0.25f);
            c.y = 0.5f * c.y + 0.5f * ((((u.y + d.y) + l.y) + r.y) * 0.25f);
            c.z = 0.5f * c.z + 0.5f * ((((u.z + d.z) + l.z) + r.z) * 0.25f);
            c.w = 0.5f * c.w + 0.5f * ((((u.w + d.w) + l.w) + r.w) * 0.25f);
        }
    }
    o[i] = c;
}

// ---------------------------------------------------------------------------
extern "C" void kernel_launch(void* const* d_in, const int* in_sizes, int n_in,
                              void* d_out, int out_size) {
    const float* x = (const float*)d_in[0];
    float* out = (float*)d_out;

    edge_kernel<<<NE, 192>>>(x);
    apply_kernel<<<NB * NPOS, 192>>>(x, out);
}